// round 4
// baseline (speedup 1.0000x reference)
#include <cuda_runtime.h>
#include <math.h>

#define B 64
#define TENC 300
#define TDEC 500
#define D 512
#define MEL 80
#define PRE 256
#define CLOC 32
#define KW 31
#define G 2048
#define KATT 1280
#define KDEC 1536
#define NSPLIT 8
#define QSPLIT 4
#define CHUNK 60
#define NCHUNK 5

// ---------------- persistent device state ----------------
__device__ float g_xatt[B * KATT];          // [pm(256) | ctx(512) | h_att(512)]
__device__ float g_xdec[B * KDEC];          // [h_att(512) | ctx(512) | h_dec(512)]
__device__ float g_catt[B * D];
__device__ float g_cdec[B * D];
__device__ float g_a[B * TENC];
__device__ float g_acum[B * TENC];
__device__ float g_e[B * TENC];
__device__ float g_conv[B * CLOC * TENC];
__device__ float g_parts[NSPLIT * B * G];
__device__ float g_qpart[QSPLIT * B * D];
__device__ float g_mproj[B * TENC * D];
__device__ float g_attW[G * KATT];
__device__ float g_decW[G * KDEC];
__device__ float g_attB[G];
__device__ float g_decB[G];
__device__ unsigned g_count;
__device__ volatile unsigned g_sense;

__device__ __forceinline__ float sigm(float x) { return 1.f / (1.f + expf(-x)); }

// ---------------- grid barrier (grid sized to guaranteed residency at launch) ----------------
__device__ __forceinline__ void gbar(unsigned ph) {
    __syncthreads();
    if (threadIdx.x == 0) {
        __threadfence();
        if (atomicAdd(&g_count, 1u) == gridDim.x - 1) {
            g_count = 0u;
            __threadfence();
            g_sense = ph;
        } else {
            while (g_sense < ph) { __nanosleep(32); }
            __threadfence();
        }
    }
    __syncthreads();
}

// ---------------- init / pack ----------------
__global__ void init_state_kernel() {
    int i = blockIdx.x * blockDim.x + threadIdx.x;
    int n = gridDim.x * blockDim.x;
    for (int j = i; j < B * KATT; j += n) g_xatt[j] = 0.f;
    for (int j = i; j < B * KDEC; j += n) g_xdec[j] = 0.f;
    for (int j = i; j < B * D; j += n) { g_catt[j] = 0.f; g_cdec[j] = 0.f; }
    for (int j = i; j < B * TENC; j += n) { g_a[j] = 0.f; g_acum[j] = 0.f; }
    if (i == 0) { g_count = 0u; g_sense = 0u; }
}

__global__ void pack_weights_kernel(const float* __restrict__ awih, const float* __restrict__ awhh,
                                    const float* __restrict__ abih, const float* __restrict__ abhh,
                                    const float* __restrict__ dwih, const float* __restrict__ dwhh,
                                    const float* __restrict__ dbih, const float* __restrict__ dbhh) {
    int idx = blockIdx.x * blockDim.x + threadIdx.x;
    if (idx < G * KATT) {
        int j = idx / KATT, k = idx % KATT;
        g_attW[idx] = (k < 768) ? awih[j * 768 + k] : awhh[j * 512 + (k - 768)];
    }
    if (idx < G * KDEC) {
        int j = idx / KDEC, k = idx % KDEC;
        g_decW[idx] = (k < 1024) ? dwih[j * 1024 + k] : dwhh[j * 512 + (k - 1024)];
    }
    if (idx < G) {
        g_attB[idx] = abih[idx] + abhh[idx];
        g_decB[idx] = dbih[idx] + dbhh[idx];
    }
}

// ---------------- 64x64 tile SGEMM piece (256 threads): C = X[64,kChunk] * W[n-tile,kChunk]^T ----------------
#define XSTRIDE 68
__device__ __forceinline__ void gemm_tile64(
    const float* __restrict__ X, int ldx,
    const float* __restrict__ W, int ldw,
    float* __restrict__ C, int ldc,
    int n0, int k0, int kChunk,
    const float* __restrict__ bias, float* sm) {
    float* Xs = sm;                       // [16][68]
    float* Ws = sm + 16 * XSTRIDE;        // [16][68]
    const int tid = threadIdx.x;
    const int tx = tid & 15, ty = tid >> 4;
    const int lr = tid >> 2, lc = (tid & 3) * 4;
    float acc[4][4];
#pragma unroll
    for (int i = 0; i < 4; i++)
#pragma unroll
        for (int j = 0; j < 4; j++) acc[i][j] = 0.f;

    const float* Xp = X + (long)lr * ldx + k0 + lc;
    const float* Wp = W + (long)(n0 + lr) * ldw + k0 + lc;

    for (int kk = 0; kk < kChunk; kk += 16) {
        float4 xa = *(const float4*)Xp;
        float4 wa = *(const float4*)Wp;
        Xp += 16; Wp += 16;
        __syncthreads();
        Xs[(lc + 0) * XSTRIDE + lr] = xa.x; Xs[(lc + 1) * XSTRIDE + lr] = xa.y;
        Xs[(lc + 2) * XSTRIDE + lr] = xa.z; Xs[(lc + 3) * XSTRIDE + lr] = xa.w;
        Ws[(lc + 0) * XSTRIDE + lr] = wa.x; Ws[(lc + 1) * XSTRIDE + lr] = wa.y;
        Ws[(lc + 2) * XSTRIDE + lr] = wa.z; Ws[(lc + 3) * XSTRIDE + lr] = wa.w;
        __syncthreads();
#pragma unroll
        for (int k = 0; k < 16; k++) {
            float xr[4], wr[4];
#pragma unroll
            for (int i = 0; i < 4; i++) xr[i] = Xs[k * XSTRIDE + ty * 4 + i];
#pragma unroll
            for (int j = 0; j < 4; j++) wr[j] = Ws[k * XSTRIDE + tx * 4 + j];
#pragma unroll
            for (int i = 0; i < 4; i++)
#pragma unroll
                for (int j = 0; j < 4; j++) acc[i][j] = fmaf(xr[i], wr[j], acc[i][j]);
        }
    }
    float bv[4] = {0.f, 0.f, 0.f, 0.f};
    if (bias) {
#pragma unroll
        for (int j = 0; j < 4; j++) bv[j] = bias[n0 + tx * 4 + j];
    }
#pragma unroll
    for (int i = 0; i < 4; i++) {
        float4 o;
        o.x = acc[i][0] + bv[0]; o.y = acc[i][1] + bv[1];
        o.z = acc[i][2] + bv[2]; o.w = acc[i][3] + bv[3];
        *(float4*)&C[(long)(ty * 4 + i) * ldc + n0 + tx * 4] = o;
    }
}

// ---------------- mproj = enc @ mem_w^T + mem_b (once per replay) ----------------
__global__ __launch_bounds__(256) void mproj_kernel(const float* __restrict__ enc,
                                                    const float* __restrict__ memw,
                                                    const float* __restrict__ memb) {
    __shared__ float sm[2 * 16 * XSTRIDE];
    int m0 = blockIdx.y * 64;
    gemm_tile64(enc + (long)m0 * D, D, memw, D, g_mproj + (long)m0 * D, D,
                blockIdx.x * 64, 0, D, memb, sm);
}

// ---------------- the persistent decoder ----------------
// smem: 2048 floats (8 KB) — enough for every stage below.
__global__ __launch_bounds__(256, 2) void persist_kernel(
    const float* __restrict__ enc, const float* __restrict__ mel_in,
    const float* __restrict__ pw1, const float* __restrict__ pb1,
    const float* __restrict__ pw2, const float* __restrict__ pb2,
    const float* __restrict__ qw, const float* __restrict__ qb,
    const float* __restrict__ convw, const float* __restrict__ convb,
    const float* __restrict__ lpw, const float* __restrict__ lpb,
    const float* __restrict__ vw, const float* __restrict__ vb,
    const float* __restrict__ melw, const float* __restrict__ melb,
    const float* __restrict__ stopw, const float* __restrict__ stopb,
    float* __restrict__ out) {
    __shared__ float sm[2176];   // 8.5 KB
    const int tid = threadIdx.x;
    unsigned ph = 0;

    for (int t = 0; t < TDEC; t++) {
        // ---- Stage A: prenet (units 0..63) + location conv (units 64..127) ----
        for (int u = blockIdx.x; u < 128; u += gridDim.x) {
            if (u < 64) {
                const int b = u;
                float* melS = sm;
                float* h1 = sm + 128;
                if (tid < MEL) melS[tid] = mel_in[(b * TDEC + t) * MEL + tid];
                __syncthreads();
                float acc = pb1[tid];
                const float* wr = pw1 + tid * MEL;
#pragma unroll 8
                for (int k = 0; k < MEL; k++) acc = fmaf(melS[k], wr[k], acc);
                h1[tid] = fmaxf(acc, 0.f);
                __syncthreads();
                float acc2 = pb2[tid];
                const float* w2r = pw2 + tid * PRE;
#pragma unroll 8
                for (int k = 0; k < PRE; k++) acc2 = fmaf(h1[k], w2r[k], acc2);
                g_xatt[b * KATT + tid] = fmaxf(acc2, 0.f);
                __syncthreads();
            } else {
                const int b = u - 64;
                float* aS = sm;            // 300
                float* acS = sm + 304;     // 300
                // conv weights stay in global (read-only cached, 7.75 KB, hot in L2)
                for (int i = tid; i < TENC; i += 256) {
                    aS[i] = g_a[b * TENC + i];
                    acS[i] = g_acum[b * TENC + i];
                }
                __syncthreads();
                for (int i = tid; i < CLOC * TENC; i += 256) {
                    int c = i / TENC, tt = i % TENC;
                    const float* w0 = convw + c * 62;
                    const float* w1 = w0 + KW;
                    float s = convb[c];
                    int klo = max(0, 15 - tt);
                    int khi = min(KW, TENC + 15 - tt);
                    for (int k = klo; k < khi; k++) {
                        int tj = tt - 15 + k;
                        s = fmaf(aS[tj], w0[k], s);
                        s = fmaf(acS[tj], w1[k], s);
                    }
                    g_conv[(b * CLOC + c) * TENC + tt] = s;
                }
                __syncthreads();
            }
        }
        gbar(++ph);

        // ---- Stage B: att gate GEMM  [64,1280]x[2048,1280]^T, K-split 8 ----
        for (int u = blockIdx.x; u < 32 * NSPLIT; u += gridDim.x) {
            int nt = u & 31, ks = u >> 5;
            gemm_tile64(g_xatt, KATT, g_attW, KATT,
                        g_parts + (long)ks * (B * G), G,
                        nt * 64, ks * (KATT / NSPLIT), KATT / NSPLIT, nullptr, sm);
        }
        gbar(++ph);

        // ---- Stage C: att LSTM update ----
        for (int u = blockIdx.x; u < 64; u += gridDim.x) {
            const int b = u;
            for (int uu = tid; uu < D; uu += 256) {
                float gi = 0.f, gf = 0.f, gg = 0.f, go = 0.f;
#pragma unroll
                for (int s = 0; s < NSPLIT; s++) {
                    const float* ps = g_parts + (long)s * (B * G) + b * G;
                    gi += ps[uu]; gf += ps[uu + 512]; gg += ps[uu + 1024]; go += ps[uu + 1536];
                }
                gi += g_attB[uu]; gf += g_attB[uu + 512];
                gg += g_attB[uu + 1024]; go += g_attB[uu + 1536];
                float c = g_catt[b * D + uu];
                c = sigm(gf) * c + sigm(gi) * tanhf(gg);
                float h = sigm(go) * tanhf(c);
                g_catt[b * D + uu] = c;
                g_xatt[b * KATT + 768 + uu] = h;
                g_xdec[b * KDEC + uu] = h;
            }
        }
        gbar(++ph);

        // ---- Stage D: q = h_att @ q_w^T, K-split 4 ----
        for (int u = blockIdx.x; u < 8 * QSPLIT; u += gridDim.x) {
            int nt = u & 7, ks = u >> 3;
            gemm_tile64(g_xdec, KDEC, qw, D,
                        g_qpart + (long)ks * (B * D), D,
                        nt * 64, ks * (D / QSPLIT), D / QSPLIT, nullptr, sm);
        }
        gbar(++ph);

        // ---- Stage E: energy = v . tanh(q + mproj + loc_proj(conv)) ----
        for (int u = blockIdx.x; u < B * NCHUNK; u += gridDim.x) {
            const int b = u / NCHUNK;
            const int t0 = (u % NCHUNK) * CHUNK;
            float* convS = sm;                          // [32][60] = 1920
            float* red = sm + CLOC * CHUNK;             // [8][6]
            for (int i = tid; i < CLOC * CHUNK; i += 256)
                convS[i] = g_conv[(b * CLOC + i / CHUNK) * TENC + t0 + (i % CHUNK)];
            const int d0 = tid, d1 = tid + 256;
            float P0[CLOC], P1[CLOC];
#pragma unroll
            for (int c = 0; c < CLOC; c++) {
                P0[c] = lpw[d0 * CLOC + c];
                P1[c] = lpw[d1 * CLOC + c];
            }
            float base0 = qb[d0] + lpb[d0];
            float base1 = qb[d1] + lpb[d1];
#pragma unroll
            for (int s = 0; s < QSPLIT; s++) {
                base0 += g_qpart[(long)s * (B * D) + b * D + d0];
                base1 += g_qpart[(long)s * (B * D) + b * D + d1];
            }
            const float v0 = vw[d0], v1 = vw[d1];
            __syncthreads();
            for (int tb = 0; tb < CHUNK; tb += 6) {
                float s0[6], s1[6];
#pragma unroll
                for (int j = 0; j < 6; j++) {
                    int tt = t0 + tb + j;
                    s0[j] = base0 + g_mproj[(long)(b * TENC + tt) * D + d0];
                    s1[j] = base1 + g_mproj[(long)(b * TENC + tt) * D + d1];
                }
#pragma unroll
                for (int c = 0; c < CLOC; c++) {
#pragma unroll
                    for (int j = 0; j < 6; j++) {
                        float cv = convS[c * CHUNK + tb + j];
                        s0[j] = fmaf(P0[c], cv, s0[j]);
                        s1[j] = fmaf(P1[c], cv, s1[j]);
                    }
                }
#pragma unroll
                for (int j = 0; j < 6; j++) {
                    float r = v0 * tanhf(s0[j]) + v1 * tanhf(s1[j]);
#pragma unroll
                    for (int o = 16; o; o >>= 1) r += __shfl_down_sync(0xffffffffu, r, o);
                    if ((tid & 31) == 0) red[(tid >> 5) * 6 + j] = r;
                }
                __syncthreads();
                if (tid < 6) {
                    float r = 0.f;
#pragma unroll
                    for (int w = 0; w < 8; w++) r += red[w * 6 + tid];
                    g_e[b * TENC + t0 + tb + tid] = r + vb[0];
                }
                __syncthreads();
            }
        }
        gbar(++ph);

        // ---- Stage F: softmax + context ----
        for (int u = blockIdx.x; u < 64; u += gridDim.x) {
            const int b = u;
            float* aS = sm;          // 300
            float* red = sm + 304;   // 8
            float* bval = sm + 314;
            float x0 = g_e[b * TENC + tid];
            float x1 = (tid + 256 < TENC) ? g_e[b * TENC + tid + 256] : -1e30f;
            float m = fmaxf(x0, x1);
#pragma unroll
            for (int o = 16; o; o >>= 1) m = fmaxf(m, __shfl_xor_sync(0xffffffffu, m, o));
            if ((tid & 31) == 0) red[tid >> 5] = m;
            __syncthreads();
            if (tid == 0) {
                float mm = red[0];
#pragma unroll
                for (int w = 1; w < 8; w++) mm = fmaxf(mm, red[w]);
                bval[0] = mm;
            }
            __syncthreads();
            const float M = bval[0];
            float e0 = expf(x0 - M);
            float e1 = (tid + 256 < TENC) ? expf(x1 - M) : 0.f;
            float s = e0 + e1;
#pragma unroll
            for (int o = 16; o; o >>= 1) s += __shfl_xor_sync(0xffffffffu, s, o);
            if ((tid & 31) == 0) red[tid >> 5] = s;
            __syncthreads();
            if (tid == 0) {
                float ss = 0.f;
#pragma unroll
                for (int w = 0; w < 8; w++) ss += red[w];
                bval[0] = 1.f / ss;
            }
            __syncthreads();
            const float inv = bval[0];
            float a0 = e0 * inv;
            aS[tid] = a0;
            g_a[b * TENC + tid] = a0;
            g_acum[b * TENC + tid] += a0;
            if (tid + 256 < TENC) {
                float a1 = e1 * inv;
                aS[tid + 256] = a1;
                g_a[b * TENC + tid + 256] = a1;
                g_acum[b * TENC + tid + 256] += a1;
            }
            __syncthreads();
            const int d0 = tid, d1 = tid + 256;
            float c0 = 0.f, c1 = 0.f;
            const float* ep = enc + (long)b * TENC * D;
#pragma unroll 4
            for (int tt = 0; tt < TENC; tt++) {
                float av = aS[tt];
                c0 = fmaf(av, ep[(long)tt * D + d0], c0);
                c1 = fmaf(av, ep[(long)tt * D + d1], c1);
            }
            g_xatt[b * KATT + 256 + d0] = c0;
            g_xatt[b * KATT + 256 + d1] = c1;
            g_xdec[b * KDEC + 512 + d0] = c0;
            g_xdec[b * KDEC + 512 + d1] = c1;
            __syncthreads();
        }
        gbar(++ph);

        // ---- Stage G: dec gate GEMM  [64,1536]x[2048,1536]^T, K-split 8 ----
        for (int u = blockIdx.x; u < 32 * NSPLIT; u += gridDim.x) {
            int nt = u & 31, ks = u >> 5;
            gemm_tile64(g_xdec, KDEC, g_decW, KDEC,
                        g_parts + (long)ks * (B * G), G,
                        nt * 64, ks * (KDEC / NSPLIT), KDEC / NSPLIT, nullptr, sm);
        }
        gbar(++ph);

        // ---- Stage H: dec LSTM + mel/stop projection (fused) ----
        for (int u = blockIdx.x; u < 64; u += gridDim.x) {
            const int b = u;
            float* hS = sm;  // 512
            for (int uu = tid; uu < D; uu += 256) {
                float gi = 0.f, gf = 0.f, gg = 0.f, go = 0.f;
#pragma unroll
                for (int s = 0; s < NSPLIT; s++) {
                    const float* ps = g_parts + (long)s * (B * G) + b * G;
                    gi += ps[uu]; gf += ps[uu + 512]; gg += ps[uu + 1024]; go += ps[uu + 1536];
                }
                gi += g_decB[uu]; gf += g_decB[uu + 512];
                gg += g_decB[uu + 1024]; go += g_decB[uu + 1536];
                float c = g_cdec[b * D + uu];
                c = sigm(gf) * c + sigm(gi) * tanhf(gg);
                float h = sigm(go) * tanhf(c);
                g_cdec[b * D + uu] = c;
                g_xdec[b * KDEC + 1024 + uu] = h;
                hS[uu] = h;
            }
            __syncthreads();
            const int warp = tid >> 5, lane = tid & 31;
            for (int n = warp; n < MEL + 1; n += 8) {
                const float* w = (n < MEL) ? (melw + n * D) : stopw;
                float acc = 0.f;
#pragma unroll
                for (int k = lane * 4; k < D; k += 128) {
                    float4 wv = *(const float4*)(w + k);
                    acc = fmaf(hS[k + 0], wv.x, acc);
                    acc = fmaf(hS[k + 1], wv.y, acc);
                    acc = fmaf(hS[k + 2], wv.z, acc);
                    acc = fmaf(hS[k + 3], wv.w, acc);
                }
#pragma unroll
                for (int o = 16; o; o >>= 1) acc += __shfl_down_sync(0xffffffffu, acc, o);
                if (lane == 0) {
                    if (n < MEL) out[(b * TDEC + t) * MEL + n] = acc + melb[n];
                    else out[B * TDEC * MEL + b * TDEC + t] = acc + stopb[0];
                }
            }
            __syncthreads();
        }
        // next iteration's Stage-A barrier orders H's writes before Stage B reads.
    }
}

// ---------------- host launch ----------------
extern "C" void kernel_launch(void* const* d_in, const int* in_sizes, int n_in,
                              void* d_out, int out_size) {
    const float* enc    = (const float*)d_in[0];
    const float* mel_in = (const float*)d_in[1];
    const float* pw1    = (const float*)d_in[2];
    const float* pb1    = (const float*)d_in[3];
    const float* pw2    = (const float*)d_in[4];
    const float* pb2    = (const float*)d_in[5];
    const float* awih   = (const float*)d_in[6];
    const float* awhh   = (const float*)d_in[7];
    const float* abih   = (const float*)d_in[8];
    const float* abhh   = (const float*)d_in[9];
    const float* dwih   = (const float*)d_in[10];
    const float* dwhh   = (const float*)d_in[11];
    const float* dbih   = (const float*)d_in[12];
    const float* dbhh   = (const float*)d_in[13];
    const float* qw     = (const float*)d_in[14];
    const float* qb     = (const float*)d_in[15];
    const float* memw   = (const float*)d_in[16];
    const float* memb   = (const float*)d_in[17];
    const float* convw  = (const float*)d_in[18];
    const float* convb  = (const float*)d_in[19];
    const float* lpw    = (const float*)d_in[20];
    const float* lpb    = (const float*)d_in[21];
    const float* vw     = (const float*)d_in[22];
    const float* vb     = (const float*)d_in[23];
    const float* melw   = (const float*)d_in[24];
    const float* melb   = (const float*)d_in[25];
    const float* stopw  = (const float*)d_in[26];
    const float* stopb  = (const float*)d_in[27];
    float* out = (float*)d_out;

    int dev = 0;
    cudaGetDevice(&dev);
    int nsm = 0;
    cudaDeviceGetAttribute(&nsm, cudaDevAttrMultiProcessorCount, dev);
    // Guaranteed-resident grid: query actual achievable occupancy for this kernel.
    int occ = 0;
    cudaOccupancyMaxActiveBlocksPerMultiprocessor(&occ, persist_kernel, 256, 0);
    if (occ < 1) occ = 1;
    if (occ > 2) occ = 2;
    int nblk = nsm * occ;

    init_state_kernel<<<64, 256>>>();
    pack_weights_kernel<<<(G * KDEC + 255) / 256, 256>>>(awih, awhh, abih, abhh,
                                                         dwih, dwhh, dbih, dbhh);
    mproj_kernel<<<dim3(8, (B * TENC) / 64), 256>>>(enc, memw, memb);
    persist_kernel<<<nblk, 256>>>(enc, mel_in, pw1, pb1, pw2, pb2, qw, qb,
                                  convw, convb, lpw, lpb, vw, vb,
                                  melw, melb, stopw, stopb, out);
}

// round 10
// speedup vs baseline: 1.1248x; 1.1248x over previous
#include <cuda_runtime.h>
#include <math.h>

#define B 64
#define TENC 300
#define TDEC 500
#define D 512
#define MEL 80
#define PRE 256
#define CLOC 32
#define KW 31
#define G 2048
#define KATT 1280
#define KDEC 1536
#define NSPLIT 8
#define QSPLIT 4
#define CHUNK 60
#define NCHUNK 5

// ---------------- persistent device state ----------------
__device__ float g_xatt[B * KATT];          // [pm(256) | ctx(512) | h_att(512)]
__device__ float g_xdec[B * KDEC];          // [h_att(512) | ctx(512) | h_dec(512)]
__device__ float g_catt[B * D];
__device__ float g_cdec[B * D];
__device__ float g_a[B * TENC];
__device__ float g_acum[B * TENC];
__device__ float g_e[B * TENC];
__device__ float g_conv[B * CLOC * TENC];
__device__ float g_parts[NSPLIT * B * G];
__device__ float g_qpart[QSPLIT * B * D];
__device__ float g_mproj[B * TENC * D];
__device__ float g_attW[G * KATT];
__device__ float g_decW[G * KDEC];
__device__ float g_attB[G];
__device__ float g_decB[G];
__device__ unsigned g_count;
__device__ volatile unsigned g_sense;

__device__ __forceinline__ float sigm(float x) { return 1.f / (1.f + expf(-x)); }

// ---------------- grid barrier (round-4 proven) ----------------
__device__ __forceinline__ void gbar(unsigned ph) {
    __syncthreads();
    if (threadIdx.x == 0) {
        __threadfence();
        if (atomicAdd(&g_count, 1u) == gridDim.x - 1) {
            g_count = 0u;
            __threadfence();
            g_sense = ph;
        } else {
            while (g_sense < ph) { __nanosleep(32); }
            __threadfence();
        }
    }
    __syncthreads();
}

// ---------------- init / pack ----------------
__global__ void init_state_kernel() {
    int i = blockIdx.x * blockDim.x + threadIdx.x;
    int n = gridDim.x * blockDim.x;
    for (int j = i; j < B * KATT; j += n) g_xatt[j] = 0.f;
    for (int j = i; j < B * KDEC; j += n) g_xdec[j] = 0.f;
    for (int j = i; j < B * D; j += n) { g_catt[j] = 0.f; g_cdec[j] = 0.f; }
    for (int j = i; j < B * TENC; j += n) { g_a[j] = 0.f; g_acum[j] = 0.f; }
    if (i == 0) { g_count = 0u; g_sense = 0u; }
}

__global__ void pack_weights_kernel(const float* __restrict__ awih, const float* __restrict__ awhh,
                                    const float* __restrict__ abih, const float* __restrict__ abhh,
                                    const float* __restrict__ dwih, const float* __restrict__ dwhh,
                                    const float* __restrict__ dbih, const float* __restrict__ dbhh) {
    int idx = blockIdx.x * blockDim.x + threadIdx.x;
    if (idx < G * KATT) {
        int j = idx / KATT, k = idx % KATT;
        g_attW[idx] = (k < 768) ? awih[j * 768 + k] : awhh[j * 512 + (k - 768)];
    }
    if (idx < G * KDEC) {
        int j = idx / KDEC, k = idx % KDEC;
        g_decW[idx] = (k < 1024) ? dwih[j * 1024 + k] : dwhh[j * 512 + (k - 1024)];
    }
    if (idx < G) {
        g_attB[idx] = abih[idx] + abhh[idx];
        g_decB[idx] = dbih[idx] + dbhh[idx];
    }
}

// ---------------- 64x64 tile SGEMM piece (256 threads) ----------------
#define XSTRIDE 68
__device__ __forceinline__ void gemm_tile64(
    const float* __restrict__ X, int ldx,
    const float* __restrict__ W, int ldw,
    float* __restrict__ C, int ldc,
    int n0, int k0, int kChunk,
    const float* __restrict__ bias, float* sm) {
    float* Xs = sm;                       // [16][68]
    float* Ws = sm + 16 * XSTRIDE;        // [16][68]
    const int tid = threadIdx.x;
    const int tx = tid & 15, ty = tid >> 4;
    const int lr = tid >> 2, lc = (tid & 3) * 4;
    float acc[4][4];
#pragma unroll
    for (int i = 0; i < 4; i++)
#pragma unroll
        for (int j = 0; j < 4; j++) acc[i][j] = 0.f;

    const float* Xp = X + (long)lr * ldx + k0 + lc;
    const float* Wp = W + (long)(n0 + lr) * ldw + k0 + lc;

    for (int kk = 0; kk < kChunk; kk += 16) {
        float4 xa = *(const float4*)Xp;
        float4 wa = *(const float4*)Wp;
        Xp += 16; Wp += 16;
        __syncthreads();
        Xs[(lc + 0) * XSTRIDE + lr] = xa.x; Xs[(lc + 1) * XSTRIDE + lr] = xa.y;
        Xs[(lc + 2) * XSTRIDE + lr] = xa.z; Xs[(lc + 3) * XSTRIDE + lr] = xa.w;
        Ws[(lc + 0) * XSTRIDE + lr] = wa.x; Ws[(lc + 1) * XSTRIDE + lr] = wa.y;
        Ws[(lc + 2) * XSTRIDE + lr] = wa.z; Ws[(lc + 3) * XSTRIDE + lr] = wa.w;
        __syncthreads();
#pragma unroll
        for (int k = 0; k < 16; k++) {
            float xr[4], wr[4];
#pragma unroll
            for (int i = 0; i < 4; i++) xr[i] = Xs[k * XSTRIDE + ty * 4 + i];
#pragma unroll
            for (int j = 0; j < 4; j++) wr[j] = Ws[k * XSTRIDE + tx * 4 + j];
#pragma unroll
            for (int i = 0; i < 4; i++)
#pragma unroll
                for (int j = 0; j < 4; j++) acc[i][j] = fmaf(xr[i], wr[j], acc[i][j]);
        }
    }
    float bv[4] = {0.f, 0.f, 0.f, 0.f};
    if (bias) {
#pragma unroll
        for (int j = 0; j < 4; j++) bv[j] = bias[n0 + tx * 4 + j];
    }
#pragma unroll
    for (int i = 0; i < 4; i++) {
        float4 o;
        o.x = acc[i][0] + bv[0]; o.y = acc[i][1] + bv[1];
        o.z = acc[i][2] + bv[2]; o.w = acc[i][3] + bv[3];
        *(float4*)&C[(long)(ty * 4 + i) * ldc + n0 + tx * 4] = o;
    }
}

// ---------------- mproj = enc @ mem_w^T + mem_b (once per replay) ----------------
__global__ __launch_bounds__(256) void mproj_kernel(const float* __restrict__ enc,
                                                    const float* __restrict__ memw,
                                                    const float* __restrict__ memb) {
    __shared__ float sm[2 * 16 * XSTRIDE];
    int m0 = blockIdx.y * 64;
    gemm_tile64(enc + (long)m0 * D, D, memw, D, g_mproj + (long)m0 * D, D,
                blockIdx.x * 64, 0, D, memb, sm);
}

// ---------------- the persistent decoder ----------------
__global__ __launch_bounds__(256, 2) void persist_kernel(
    const float* __restrict__ enc, const float* __restrict__ mel_in,
    const float* __restrict__ pw1, const float* __restrict__ pb1,
    const float* __restrict__ pw2, const float* __restrict__ pb2,
    const float* __restrict__ qw, const float* __restrict__ qb,
    const float* __restrict__ convw, const float* __restrict__ convb,
    const float* __restrict__ lpw, const float* __restrict__ lpb,
    const float* __restrict__ vw, const float* __restrict__ vb,
    const float* __restrict__ melw, const float* __restrict__ melb,
    const float* __restrict__ stopw, const float* __restrict__ stopb,
    float* __restrict__ out) {
    __shared__ float sm[2176];   // 8.5 KB
    const int tid = threadIdx.x;
    unsigned ph = 0;

    for (int t = 0; t < TDEC; t++) {
        // ---- Stage A: prenet (units 0..63) + location conv (units 64..127) ----
        for (int u = blockIdx.x; u < 128; u += gridDim.x) {
            if (u < 64) {
                const int b = u;
                float* melS = sm;
                float* h1 = sm + 128;
                if (tid < MEL) melS[tid] = mel_in[(b * TDEC + t) * MEL + tid];
                __syncthreads();
                float acc = pb1[tid];
                const float* wr = pw1 + tid * MEL;
#pragma unroll 8
                for (int k = 0; k < MEL; k++) acc = fmaf(melS[k], wr[k], acc);
                h1[tid] = fmaxf(acc, 0.f);
                __syncthreads();
                float acc2 = pb2[tid];
                const float* w2r = pw2 + tid * PRE;
#pragma unroll 8
                for (int k = 0; k < PRE; k++) acc2 = fmaf(h1[k], w2r[k], acc2);
                g_xatt[b * KATT + tid] = fmaxf(acc2, 0.f);
                __syncthreads();
            } else {
                const int b = u - 64;
                float* aS = sm;            // 300
                float* acS = sm + 304;     // 300
                for (int i = tid; i < TENC; i += 256) {
                    aS[i] = g_a[b * TENC + i];
                    acS[i] = g_acum[b * TENC + i];
                }
                __syncthreads();
                for (int i = tid; i < CLOC * TENC; i += 256) {
                    int c = i / TENC, tt = i % TENC;
                    const float* w0 = convw + c * 62;
                    const float* w1 = w0 + KW;
                    float s = convb[c];
                    int klo = max(0, 15 - tt);
                    int khi = min(KW, TENC + 15 - tt);
                    for (int k = klo; k < khi; k++) {
                        int tj = tt - 15 + k;
                        s = fmaf(aS[tj], w0[k], s);
                        s = fmaf(acS[tj], w1[k], s);
                    }
                    g_conv[(b * CLOC + c) * TENC + tt] = s;
                }
                __syncthreads();
            }
        }
        gbar(++ph);

        // ---- Stage B: att gate GEMM  [64,1280]x[2048,1280]^T, K-split 8 ----
        for (int u = blockIdx.x; u < 32 * NSPLIT; u += gridDim.x) {
            int nt = u & 31, ks = u >> 5;
            gemm_tile64(g_xatt, KATT, g_attW, KATT,
                        g_parts + (long)ks * (B * G), G,
                        nt * 64, ks * (KATT / NSPLIT), KATT / NSPLIT, nullptr, sm);
        }
        gbar(++ph);

        // ---- Stage C: att LSTM update (spread over 128 blocks: b x half) ----
        for (int u = blockIdx.x; u < 128; u += gridDim.x) {
            const int b = u >> 1;
            const int uu = (u & 1) * 256 + tid;
            float gi = 0.f, gf = 0.f, gg = 0.f, go = 0.f;
#pragma unroll
            for (int s = 0; s < NSPLIT; s++) {
                const float* ps = g_parts + (long)s * (B * G) + b * G;
                gi += ps[uu]; gf += ps[uu + 512]; gg += ps[uu + 1024]; go += ps[uu + 1536];
            }
            gi += g_attB[uu]; gf += g_attB[uu + 512];
            gg += g_attB[uu + 1024]; go += g_attB[uu + 1536];
            float c = g_catt[b * D + uu];
            c = sigm(gf) * c + sigm(gi) * tanhf(gg);
            float h = sigm(go) * tanhf(c);
            g_catt[b * D + uu] = c;
            g_xatt[b * KATT + 768 + uu] = h;
            g_xdec[b * KDEC + uu] = h;
        }
        gbar(++ph);

        // ---- Stage D: q = h_att @ q_w^T, K-split 4 ----
        for (int u = blockIdx.x; u < 8 * QSPLIT; u += gridDim.x) {
            int nt = u & 7, ks = u >> 3;
            gemm_tile64(g_xdec, KDEC, qw, D,
                        g_qpart + (long)ks * (B * D), D,
                        nt * 64, ks * (D / QSPLIT), D / QSPLIT, nullptr, sm);
        }
        gbar(++ph);

        // ---- Stage E: energy = v . tanh(q + mproj + loc_proj(conv)) ----
        for (int u = blockIdx.x; u < B * NCHUNK; u += gridDim.x) {
            const int b = u / NCHUNK;
            const int t0 = (u % NCHUNK) * CHUNK;
            float* convS = sm;                          // [32][60] = 1920
            float* red = sm + CLOC * CHUNK;             // [8][6]
            for (int i = tid; i < CLOC * CHUNK; i += 256)
                convS[i] = g_conv[(b * CLOC + i / CHUNK) * TENC + t0 + (i % CHUNK)];
            const int d0 = tid, d1 = tid + 256;
            float P0[CLOC], P1[CLOC];
#pragma unroll
            for (int c = 0; c < CLOC; c++) {
                P0[c] = lpw[d0 * CLOC + c];
                P1[c] = lpw[d1 * CLOC + c];
            }
            float base0 = qb[d0] + lpb[d0];
            float base1 = qb[d1] + lpb[d1];
#pragma unroll
            for (int s = 0; s < QSPLIT; s++) {
                base0 += g_qpart[(long)s * (B * D) + b * D + d0];
                base1 += g_qpart[(long)s * (B * D) + b * D + d1];
            }
            const float v0 = vw[d0], v1 = vw[d1];
            __syncthreads();
            for (int tb = 0; tb < CHUNK; tb += 6) {
                float s0[6], s1[6];
#pragma unroll
                for (int j = 0; j < 6; j++) {
                    int tt = t0 + tb + j;
                    s0[j] = base0 + g_mproj[(long)(b * TENC + tt) * D + d0];
                    s1[j] = base1 + g_mproj[(long)(b * TENC + tt) * D + d1];
                }
#pragma unroll
                for (int c = 0; c < CLOC; c++) {
#pragma unroll
                    for (int j = 0; j < 6; j++) {
                        float cv = convS[c * CHUNK + tb + j];
                        s0[j] = fmaf(P0[c], cv, s0[j]);
                        s1[j] = fmaf(P1[c], cv, s1[j]);
                    }
                }
#pragma unroll
                for (int j = 0; j < 6; j++) {
                    float r = v0 * tanhf(s0[j]) + v1 * tanhf(s1[j]);
#pragma unroll
                    for (int o = 16; o; o >>= 1) r += __shfl_down_sync(0xffffffffu, r, o);
                    if ((tid & 31) == 0) red[(tid >> 5) * 6 + j] = r;
                }
                __syncthreads();
                if (tid < 6) {
                    float r = 0.f;
#pragma unroll
                    for (int w = 0; w < 8; w++) r += red[w * 6 + tid];
                    g_e[b * TENC + t0 + tb + tid] = r + vb[0];
                }
                __syncthreads();
            }
        }
        gbar(++ph);

        // ---- Stage F1: softmax (64 blocks) ----
        for (int u = blockIdx.x; u < 64; u += gridDim.x) {
            const int b = u;
            float* red = sm;           // 8
            float* bval = sm + 10;
            float x0 = g_e[b * TENC + tid];
            float x1 = (tid + 256 < TENC) ? g_e[b * TENC + tid + 256] : -1e30f;
            float m = fmaxf(x0, x1);
#pragma unroll
            for (int o = 16; o; o >>= 1) m = fmaxf(m, __shfl_xor_sync(0xffffffffu, m, o));
            if ((tid & 31) == 0) red[tid >> 5] = m;
            __syncthreads();
            if (tid == 0) {
                float mm = red[0];
#pragma unroll
                for (int w = 1; w < 8; w++) mm = fmaxf(mm, red[w]);
                bval[0] = mm;
            }
            __syncthreads();
            const float M = bval[0];
            float e0 = expf(x0 - M);
            float e1 = (tid + 256 < TENC) ? expf(x1 - M) : 0.f;
            float s = e0 + e1;
#pragma unroll
            for (int o = 16; o; o >>= 1) s += __shfl_xor_sync(0xffffffffu, s, o);
            if ((tid & 31) == 0) red[tid >> 5] = s;
            __syncthreads();
            if (tid == 0) {
                float ss = 0.f;
#pragma unroll
                for (int w = 0; w < 8; w++) ss += red[w];
                bval[0] = 1.f / ss;
            }
            __syncthreads();
            const float inv = bval[0];
            float a0 = e0 * inv;
            g_a[b * TENC + tid] = a0;
            g_acum[b * TENC + tid] += a0;
            if (tid + 256 < TENC) {
                float a1 = e1 * inv;
                g_a[b * TENC + tid + 256] = a1;
                g_acum[b * TENC + tid + 256] += a1;
            }
            __syncthreads();
        }
        gbar(++ph);

        // ---- Stage F2: ctx = a @ enc[b]  (256 blocks: b x 128-d range) ----
        for (int u = blockIdx.x; u < 256; u += gridDim.x) {
            const int b = u >> 2;
            const int dq = u & 3;
            float* aS = sm;            // 300
            float* part = sm + 304;    // [2][128]
            for (int i = tid; i < TENC; i += 256) aS[i] = g_a[b * TENC + i];
            __syncthreads();
            const int dl = tid & 127;
            const int th = tid >> 7;                 // t-half 0/1
            const float* ep = enc + (long)b * TENC * D + dq * 128 + dl;
            float acc = 0.f;
#pragma unroll 10
            for (int tt = th * 150; tt < th * 150 + 150; tt++)
                acc = fmaf(aS[tt], ep[(long)tt * D], acc);
            part[th * 128 + dl] = acc;
            __syncthreads();
            if (tid < 128) {
                float c = part[tid] + part[128 + tid];
                g_xatt[b * KATT + 256 + dq * 128 + tid] = c;
                g_xdec[b * KDEC + 512 + dq * 128 + tid] = c;
            }
            __syncthreads();
        }
        gbar(++ph);

        // ---- Stage G: dec gate GEMM  [64,1536]x[2048,1536]^T, K-split 8 ----
        for (int u = blockIdx.x; u < 32 * NSPLIT; u += gridDim.x) {
            int nt = u & 31, ks = u >> 5;
            gemm_tile64(g_xdec, KDEC, g_decW, KDEC,
                        g_parts + (long)ks * (B * G), G,
                        nt * 64, ks * (KDEC / NSPLIT), KDEC / NSPLIT, nullptr, sm);
        }
        gbar(++ph);

        // ---- Stage H: dec LSTM + mel/stop projection ----
        for (int u = blockIdx.x; u < 64; u += gridDim.x) {
            const int b = u;
            float* hS = sm;  // 512
            for (int uu = tid; uu < D; uu += 256) {
                float gi = 0.f, gf = 0.f, gg = 0.f, go = 0.f;
#pragma unroll
                for (int s = 0; s < NSPLIT; s++) {
                    const float* ps = g_parts + (long)s * (B * G) + b * G;
                    gi += ps[uu]; gf += ps[uu + 512]; gg += ps[uu + 1024]; go += ps[uu + 1536];
                }
                gi += g_decB[uu]; gf += g_decB[uu + 512];
                gg += g_decB[uu + 1024]; go += g_decB[uu + 1536];
                float c = g_cdec[b * D + uu];
                c = sigm(gf) * c + sigm(gi) * tanhf(gg);
                float h = sigm(go) * tanhf(c);
                g_cdec[b * D + uu] = c;
                g_xdec[b * KDEC + 1024 + uu] = h;
                hS[uu] = h;
            }
            __syncthreads();
            const int warp = tid >> 5, lane = tid & 31;
            for (int n = warp; n < MEL + 1; n += 8) {
                const float* w = (n < MEL) ? (melw + n * D) : stopw;
                float acc = 0.f;
#pragma unroll
                for (int k = lane * 4; k < D; k += 128) {
                    float4 wv = *(const float4*)(w + k);
                    acc = fmaf(hS[k + 0], wv.x, acc);
                    acc = fmaf(hS[k + 1], wv.y, acc);
                    acc = fmaf(hS[k + 2], wv.z, acc);
                    acc = fmaf(hS[k + 3], wv.w, acc);
                }
#pragma unroll
                for (int o = 16; o; o >>= 1) acc += __shfl_down_sync(0xffffffffu, acc, o);
                if (lane == 0) {
                    if (n < MEL) out[(b * TDEC + t) * MEL + n] = acc + melb[n];
                    else out[B * TDEC * MEL + b * TDEC + t] = acc + stopb[0];
                }
            }
            __syncthreads();
        }
        gbar(++ph);
    }
}

// ---------------- host launch ----------------
extern "C" void kernel_launch(void* const* d_in, const int* in_sizes, int n_in,
                              void* d_out, int out_size) {
    const float* enc    = (const float*)d_in[0];
    const float* mel_in = (const float*)d_in[1];
    const float* pw1    = (const float*)d_in[2];
    const float* pb1    = (const float*)d_in[3];
    const float* pw2    = (const float*)d_in[4];
    const float* pb2    = (const float*)d_in[5];
    const float* awih   = (const float*)d_in[6];
    const float* awhh   = (const float*)d_in[7];
    const float* abih   = (const float*)d_in[8];
    const float* abhh   = (const float*)d_in[9];
    const float* dwih   = (const float*)d_in[10];
    const float* dwhh   = (const float*)d_in[11];
    const float* dbih   = (const float*)d_in[12];
    const float* dbhh   = (const float*)d_in[13];
    const float* qw     = (const float*)d_in[14];
    const float* qb     = (const float*)d_in[15];
    const float* memw   = (const float*)d_in[16];
    const float* memb   = (const float*)d_in[17];
    const float* convw  = (const float*)d_in[18];
    const float* convb  = (const float*)d_in[19];
    const float* lpw    = (const float*)d_in[20];
    const float* lpb    = (const float*)d_in[21];
    const float* vw     = (const float*)d_in[22];
    const float* vb     = (const float*)d_in[23];
    const float* melw   = (const float*)d_in[24];
    const float* melb   = (const float*)d_in[25];
    const float* stopw  = (const float*)d_in[26];
    const float* stopb  = (const float*)d_in[27];
    float* out = (float*)d_out;

    int dev = 0;
    cudaGetDevice(&dev);
    int nsm = 0;
    cudaDeviceGetAttribute(&nsm, cudaDevAttrMultiProcessorCount, dev);
    int occ = 0;
    cudaOccupancyMaxActiveBlocksPerMultiprocessor(&occ, persist_kernel, 256, 0);
    if (occ < 1) occ = 1;
    if (occ > 2) occ = 2;
    int nblk = nsm * occ;

    init_state_kernel<<<64, 256>>>();
    pack_weights_kernel<<<(G * KDEC + 255) / 256, 256>>>(awih, awhh, abih, abhh,
                                                         dwih, dwhh, dbih, dbhh);
    mproj_kernel<<<dim3(8, (B * TENC) / 64), 256>>>(enc, memw, memb);
    persist_kernel<<<nblk, 256>>>(enc, mel_in, pw1, pb1, pw2, pb2, qw, qb,
                                  convw, convb, lpw, lpb, vw, vb,
                                  melw, melb, stopw, stopb, out);
}

// round 12
// speedup vs baseline: 1.1973x; 1.0644x over previous
#include <cuda_runtime.h>
#include <math.h>

#define B 64
#define TENC 300
#define TDEC 500
#define D 512
#define MEL 80
#define PRE 256
#define CLOC 32
#define KW 31
#define G 2048
#define KATT 1280
#define KDEC 1536
#define NSPLIT 8
#define QSPLIT 4
#define CHUNK 75
#define NCHUNK 4

// ---------------- persistent device state ----------------
__device__ float g_xatt[B * KATT];          // [pm(256) | ctx(512) | h_att(512)]
__device__ float g_xdec[B * KDEC];          // [h_att(512) | ctx(512) | h_dec(512)]
__device__ float g_catt[B * D];
__device__ float g_cdec[B * D];
__device__ float g_a[B * TENC];
__device__ float g_acum[B * TENC];
__device__ float g_e[B * TENC];
__device__ float g_conv[B * CLOC * TENC];
__device__ float g_parts[NSPLIT * B * G];
__device__ float g_qpart[QSPLIT * B * D];
__device__ float g_mproj[B * TENC * D];
__device__ float g_attW[G * KATT];
__device__ float g_decW[G * KDEC];
__device__ float g_attB[G];
__device__ float g_decB[G];
__device__ unsigned g_count;
__device__ volatile unsigned g_sense;

__device__ __forceinline__ float sigm(float x) { return 1.f / (1.f + expf(-x)); }
// fast tanh used ONLY in the attention-energy stage
__device__ __forceinline__ float ftanh(float x) {
    float e = __expf(-2.f * fabsf(x));
    float r = (1.f - e) / (1.f + e);
    return x < 0.f ? -r : r;
}

// ---------------- grid barrier (round-4/10 proven) ----------------
__device__ __forceinline__ void gbar(unsigned ph) {
    __syncthreads();
    if (threadIdx.x == 0) {
        __threadfence();
        if (atomicAdd(&g_count, 1u) == gridDim.x - 1) {
            g_count = 0u;
            __threadfence();
            g_sense = ph;
        } else {
            while (g_sense < ph) { __nanosleep(32); }
            __threadfence();
        }
    }
    __syncthreads();
}

// ---------------- init / pack ----------------
__global__ void init_state_kernel() {
    int i = blockIdx.x * blockDim.x + threadIdx.x;
    int n = gridDim.x * blockDim.x;
    for (int j = i; j < B * KATT; j += n) g_xatt[j] = 0.f;
    for (int j = i; j < B * KDEC; j += n) g_xdec[j] = 0.f;
    for (int j = i; j < B * D; j += n) { g_catt[j] = 0.f; g_cdec[j] = 0.f; }
    for (int j = i; j < B * TENC; j += n) { g_a[j] = 0.f; g_acum[j] = 0.f; }
    if (i == 0) { g_count = 0u; g_sense = 0u; }
}

__global__ void pack_weights_kernel(const float* __restrict__ awih, const float* __restrict__ awhh,
                                    const float* __restrict__ abih, const float* __restrict__ abhh,
                                    const float* __restrict__ dwih, const float* __restrict__ dwhh,
                                    const float* __restrict__ dbih, const float* __restrict__ dbhh) {
    int idx = blockIdx.x * blockDim.x + threadIdx.x;
    if (idx < G * KATT) {
        int j = idx / KATT, k = idx % KATT;
        g_attW[idx] = (k < 768) ? awih[j * 768 + k] : awhh[j * 512 + (k - 768)];
    }
    if (idx < G * KDEC) {
        int j = idx / KDEC, k = idx % KDEC;
        g_decW[idx] = (k < 1024) ? dwih[j * 1024 + k] : dwhh[j * 512 + (k - 1024)];
    }
    if (idx < G) {
        g_attB[idx] = abih[idx] + abhh[idx];
        g_decB[idx] = dbih[idx] + dbhh[idx];
    }
}

// ---------------- 64x64 tile SGEMM piece (256 threads) ----------------
#define XSTRIDE 68
__device__ __forceinline__ void gemm_tile64(
    const float* __restrict__ X, int ldx,
    const float* __restrict__ W, int ldw,
    float* __restrict__ C, int ldc,
    int n0, int k0, int kChunk,
    const float* __restrict__ bias, float* sm) {
    float* Xs = sm;                       // [16][68]
    float* Ws = sm + 16 * XSTRIDE;        // [16][68]
    const int tid = threadIdx.x;
    const int tx = tid & 15, ty = tid >> 4;
    const int lr = tid >> 2, lc = (tid & 3) * 4;
    float acc[4][4];
#pragma unroll
    for (int i = 0; i < 4; i++)
#pragma unroll
        for (int j = 0; j < 4; j++) acc[i][j] = 0.f;

    const float* Xp = X + (long)lr * ldx + k0 + lc;
    const float* Wp = W + (long)(n0 + lr) * ldw + k0 + lc;

    for (int kk = 0; kk < kChunk; kk += 16) {
        float4 xa = *(const float4*)Xp;
        float4 wa = *(const float4*)Wp;
        Xp += 16; Wp += 16;
        __syncthreads();
        Xs[(lc + 0) * XSTRIDE + lr] = xa.x; Xs[(lc + 1) * XSTRIDE + lr] = xa.y;
        Xs[(lc + 2) * XSTRIDE + lr] = xa.z; Xs[(lc + 3) * XSTRIDE + lr] = xa.w;
        Ws[(lc + 0) * XSTRIDE + lr] = wa.x; Ws[(lc + 1) * XSTRIDE + lr] = wa.y;
        Ws[(lc + 2) * XSTRIDE + lr] = wa.z; Ws[(lc + 3) * XSTRIDE + lr] = wa.w;
        __syncthreads();
#pragma unroll
        for (int k = 0; k < 16; k++) {
            float xr[4], wr[4];
#pragma unroll
            for (int i = 0; i < 4; i++) xr[i] = Xs[k * XSTRIDE + ty * 4 + i];
#pragma unroll
            for (int j = 0; j < 4; j++) wr[j] = Ws[k * XSTRIDE + tx * 4 + j];
#pragma unroll
            for (int i = 0; i < 4; i++)
#pragma unroll
                for (int j = 0; j < 4; j++) acc[i][j] = fmaf(xr[i], wr[j], acc[i][j]);
        }
    }
    float bv[4] = {0.f, 0.f, 0.f, 0.f};
    if (bias) {
#pragma unroll
        for (int j = 0; j < 4; j++) bv[j] = bias[n0 + tx * 4 + j];
    }
#pragma unroll
    for (int i = 0; i < 4; i++) {
        float4 o;
        o.x = acc[i][0] + bv[0]; o.y = acc[i][1] + bv[1];
        o.z = acc[i][2] + bv[2]; o.w = acc[i][3] + bv[3];
        *(float4*)&C[(long)(ty * 4 + i) * ldc + n0 + tx * 4] = o;
    }
}

// ---------------- mproj = enc @ mem_w^T + mem_b (once per replay) ----------------
__global__ __launch_bounds__(256) void mproj_kernel(const float* __restrict__ enc,
                                                    const float* __restrict__ memw,
                                                    const float* __restrict__ memb) {
    __shared__ float sm[2 * 16 * XSTRIDE];
    int m0 = blockIdx.y * 64;
    gemm_tile64(enc + (long)m0 * D, D, memw, D, g_mproj + (long)m0 * D, D,
                blockIdx.x * 64, 0, D, memb, sm);
}

// ---------------- the persistent decoder ----------------
__global__ __launch_bounds__(256, 2) void persist_kernel(
    const float* __restrict__ enc, const float* __restrict__ mel_in,
    const float* __restrict__ pw1, const float* __restrict__ pb1,
    const float* __restrict__ pw2, const float* __restrict__ pb2,
    const float* __restrict__ qw, const float* __restrict__ qb,
    const float* __restrict__ convw, const float* __restrict__ convb,
    const float* __restrict__ lpw, const float* __restrict__ lpb,
    const float* __restrict__ vw, const float* __restrict__ vb,
    const float* __restrict__ melw, const float* __restrict__ melb,
    const float* __restrict__ stopw, const float* __restrict__ stopb,
    float* __restrict__ out) {
    __shared__ float sm[2560];   // 10 KB
    const int tid = threadIdx.x;
    unsigned ph = 0;

    for (int t = 0; t < TDEC; t++) {
        // ---- Stage A: prenet (units 0..63) + conv over (b, t-third) (units 64..255) ----
        for (int u = blockIdx.x; u < 256; u += gridDim.x) {
            if (u < 64) {
                const int b = u;
                float* melS = sm;
                float* h1 = sm + 128;
                if (tid < MEL) melS[tid] = mel_in[(b * TDEC + t) * MEL + tid];
                __syncthreads();
                float acc = pb1[tid];
                const float* wr = pw1 + tid * MEL;
#pragma unroll 8
                for (int k = 0; k < MEL; k++) acc = fmaf(melS[k], wr[k], acc);
                h1[tid] = fmaxf(acc, 0.f);
                __syncthreads();
                float acc2 = pb2[tid];
                const float* w2r = pw2 + tid * PRE;
#pragma unroll 8
                for (int k = 0; k < PRE; k++) acc2 = fmaf(h1[k], w2r[k], acc2);
                g_xatt[b * KATT + tid] = fmaxf(acc2, 0.f);
                __syncthreads();
            } else {
                const int v = u - 64;
                const int b = v / 3;
                const int t0 = (v % 3) * 100;       // t range [t0, t0+100)
                float* aS = sm;            // 300
                float* acS = sm + 304;     // 300
                for (int i = tid; i < TENC; i += 256) {
                    aS[i] = g_a[b * TENC + i];
                    acS[i] = g_acum[b * TENC + i];
                }
                __syncthreads();
                for (int i = tid; i < CLOC * 100; i += 256) {
                    int c = i / 100, tl = i % 100;
                    int tt = t0 + tl;
                    const float* w0 = convw + c * 62;
                    const float* w1 = w0 + KW;
                    float s = convb[c];
                    int klo = max(0, 15 - tt);
                    int khi = min(KW, TENC + 15 - tt);
                    for (int k = klo; k < khi; k++) {
                        int tj = tt - 15 + k;
                        s = fmaf(aS[tj], w0[k], s);
                        s = fmaf(acS[tj], w1[k], s);
                    }
                    g_conv[(b * CLOC + c) * TENC + tt] = s;
                }
                __syncthreads();
            }
        }
        gbar(++ph);

        // ---- Stage B: att gate GEMM  [64,1280]x[2048,1280]^T, K-split 8 ----
        for (int u = blockIdx.x; u < 32 * NSPLIT; u += gridDim.x) {
            int nt = u & 31, ks = u >> 5;
            gemm_tile64(g_xatt, KATT, g_attW, KATT,
                        g_parts + (long)ks * (B * G), G,
                        nt * 64, ks * (KATT / NSPLIT), KATT / NSPLIT, nullptr, sm);
        }
        gbar(++ph);

        // ---- Stage C: att LSTM update (128 blocks: b x half) ----
        for (int u = blockIdx.x; u < 128; u += gridDim.x) {
            const int b = u >> 1;
            const int uu = (u & 1) * 256 + tid;
            float gi = 0.f, gf = 0.f, gg = 0.f, go = 0.f;
#pragma unroll
            for (int s = 0; s < NSPLIT; s++) {
                const float* ps = g_parts + (long)s * (B * G) + b * G;
                gi += ps[uu]; gf += ps[uu + 512]; gg += ps[uu + 1024]; go += ps[uu + 1536];
            }
            gi += g_attB[uu]; gf += g_attB[uu + 512];
            gg += g_attB[uu + 1024]; go += g_attB[uu + 1536];
            float c = g_catt[b * D + uu];
            c = sigm(gf) * c + sigm(gi) * tanhf(gg);
            float h = sigm(go) * tanhf(c);
            g_catt[b * D + uu] = c;
            g_xatt[b * KATT + 768 + uu] = h;
            g_xdec[b * KDEC + uu] = h;
        }
        gbar(++ph);

        // ---- Stage D: q = h_att @ q_w^T, K-split 4 ----
        for (int u = blockIdx.x; u < 8 * QSPLIT; u += gridDim.x) {
            int nt = u & 7, ks = u >> 3;
            gemm_tile64(g_xdec, KDEC, qw, D,
                        g_qpart + (long)ks * (B * D), D,
                        nt * 64, ks * (D / QSPLIT), D / QSPLIT, nullptr, sm);
        }
        gbar(++ph);

        // ---- Stage E: energy = v . tanh(q + mproj + loc_proj(conv))  (256 units) ----
        for (int u = blockIdx.x; u < B * NCHUNK; u += gridDim.x) {
            const int b = u / NCHUNK;
            const int t0 = (u % NCHUNK) * CHUNK;
            float* convS = sm;                          // [32][75] = 2400
            float* red = sm + CLOC * CHUNK;             // [8][5]
            for (int i = tid; i < CLOC * CHUNK; i += 256)
                convS[i] = g_conv[(b * CLOC + i / CHUNK) * TENC + t0 + (i % CHUNK)];
            const int d0 = tid, d1 = tid + 256;
            float P0[CLOC], P1[CLOC];
#pragma unroll
            for (int c = 0; c < CLOC; c++) {
                P0[c] = lpw[d0 * CLOC + c];
                P1[c] = lpw[d1 * CLOC + c];
            }
            float base0 = qb[d0] + lpb[d0];
            float base1 = qb[d1] + lpb[d1];
#pragma unroll
            for (int s = 0; s < QSPLIT; s++) {
                base0 += g_qpart[(long)s * (B * D) + b * D + d0];
                base1 += g_qpart[(long)s * (B * D) + b * D + d1];
            }
            const float v0 = vw[d0], v1 = vw[d1];
            __syncthreads();
            for (int tb = 0; tb < CHUNK; tb += 5) {
                float s0[5], s1[5];
#pragma unroll
                for (int j = 0; j < 5; j++) {
                    int tt = t0 + tb + j;
                    s0[j] = base0 + g_mproj[(long)(b * TENC + tt) * D + d0];
                    s1[j] = base1 + g_mproj[(long)(b * TENC + tt) * D + d1];
                }
#pragma unroll
                for (int c = 0; c < CLOC; c++) {
#pragma unroll
                    for (int j = 0; j < 5; j++) {
                        float cv = convS[c * CHUNK + tb + j];
                        s0[j] = fmaf(P0[c], cv, s0[j]);
                        s1[j] = fmaf(P1[c], cv, s1[j]);
                    }
                }
#pragma unroll
                for (int j = 0; j < 5; j++) {
                    float r = v0 * ftanh(s0[j]) + v1 * ftanh(s1[j]);
#pragma unroll
                    for (int o = 16; o; o >>= 1) r += __shfl_down_sync(0xffffffffu, r, o);
                    if ((tid & 31) == 0) red[(tid >> 5) * 5 + j] = r;
                }
                __syncthreads();
                if (tid < 5) {
                    float r = 0.f;
#pragma unroll
                    for (int w = 0; w < 8; w++) r += red[w * 5 + tid];
                    g_e[b * TENC + t0 + tb + tid] = r + vb[0];
                }
                __syncthreads();
            }
        }
        gbar(++ph);

        // ---- Stage F (fused): local softmax + ctx slice (256 blocks: b x 128-d) ----
        for (int u = blockIdx.x; u < 256; u += gridDim.x) {
            const int b = u >> 2;
            const int dq = u & 3;
            float* aS = sm;            // 300
            float* part = sm + 304;    // [2][128]
            float* red = sm + 564;     // 8
            float* bval = sm + 574;
            float x0 = g_e[b * TENC + tid];
            float x1 = (tid + 256 < TENC) ? g_e[b * TENC + tid + 256] : -1e30f;
            float m = fmaxf(x0, x1);
#pragma unroll
            for (int o = 16; o; o >>= 1) m = fmaxf(m, __shfl_xor_sync(0xffffffffu, m, o));
            if ((tid & 31) == 0) red[tid >> 5] = m;
            __syncthreads();
            if (tid == 0) {
                float mm = red[0];
#pragma unroll
                for (int w = 1; w < 8; w++) mm = fmaxf(mm, red[w]);
                bval[0] = mm;
            }
            __syncthreads();
            const float M = bval[0];
            float e0 = expf(x0 - M);
            float e1 = (tid + 256 < TENC) ? expf(x1 - M) : 0.f;
            float s = e0 + e1;
#pragma unroll
            for (int o = 16; o; o >>= 1) s += __shfl_xor_sync(0xffffffffu, s, o);
            if ((tid & 31) == 0) red[tid >> 5] = s;
            __syncthreads();
            if (tid == 0) {
                float ss = 0.f;
#pragma unroll
                for (int w = 0; w < 8; w++) ss += red[w];
                bval[0] = 1.f / ss;
            }
            __syncthreads();
            const float inv = bval[0];
            float a0 = e0 * inv;
            aS[tid] = a0;
            if (tid + 256 < TENC) aS[tid + 256] = e1 * inv;
            if (dq == 0) {              // single writer commits a / a_cum
                g_a[b * TENC + tid] = a0;
                g_acum[b * TENC + tid] += a0;
                if (tid + 256 < TENC) {
                    float a1 = e1 * inv;
                    g_a[b * TENC + tid + 256] = a1;
                    g_acum[b * TENC + tid + 256] += a1;
                }
            }
            __syncthreads();
            const int dl = tid & 127;
            const int th = tid >> 7;                 // t-half 0/1
            const float* ep = enc + (long)b * TENC * D + dq * 128 + dl;
            float acc = 0.f;
#pragma unroll 10
            for (int tt = th * 150; tt < th * 150 + 150; tt++)
                acc = fmaf(aS[tt], ep[(long)tt * D], acc);
            part[th * 128 + dl] = acc;
            __syncthreads();
            if (tid < 128) {
                float c = part[tid] + part[128 + tid];
                g_xatt[b * KATT + 256 + dq * 128 + tid] = c;
                g_xdec[b * KDEC + 512 + dq * 128 + tid] = c;
            }
            __syncthreads();
        }
        gbar(++ph);

        // ---- Stage G: dec gate GEMM  [64,1536]x[2048,1536]^T, K-split 8 ----
        for (int u = blockIdx.x; u < 32 * NSPLIT; u += gridDim.x) {
            int nt = u & 31, ks = u >> 5;
            gemm_tile64(g_xdec, KDEC, g_decW, KDEC,
                        g_parts + (long)ks * (B * G), G,
                        nt * 64, ks * (KDEC / NSPLIT), KDEC / NSPLIT, nullptr, sm);
        }
        gbar(++ph);

        // ---- Stage H: dec LSTM + mel/stop projection ----
        for (int u = blockIdx.x; u < 64; u += gridDim.x) {
            const int b = u;
            float* hS = sm;  // 512
            for (int uu = tid; uu < D; uu += 256) {
                float gi = 0.f, gf = 0.f, gg = 0.f, go = 0.f;
#pragma unroll
                for (int s = 0; s < NSPLIT; s++) {
                    const float* ps = g_parts + (long)s * (B * G) + b * G;
                    gi += ps[uu]; gf += ps[uu + 512]; gg += ps[uu + 1024]; go += ps[uu + 1536];
                }
                gi += g_decB[uu]; gf += g_decB[uu + 512];
                gg += g_decB[uu + 1024]; go += g_decB[uu + 1536];
                float c = g_cdec[b * D + uu];
                c = sigm(gf) * c + sigm(gi) * tanhf(gg);
                float h = sigm(go) * tanhf(c);
                g_cdec[b * D + uu] = c;
                g_xdec[b * KDEC + 1024 + uu] = h;
                hS[uu] = h;
            }
            __syncthreads();
            const int warp = tid >> 5, lane = tid & 31;
            for (int n = warp; n < MEL + 1; n += 8) {
                const float* w = (n < MEL) ? (melw + n * D) : stopw;
                float acc = 0.f;
#pragma unroll
                for (int k = lane * 4; k < D; k += 128) {
                    float4 wv = *(const float4*)(w + k);
                    acc = fmaf(hS[k + 0], wv.x, acc);
                    acc = fmaf(hS[k + 1], wv.y, acc);
                    acc = fmaf(hS[k + 2], wv.z, acc);
                    acc = fmaf(hS[k + 3], wv.w, acc);
                }
#pragma unroll
                for (int o = 16; o; o >>= 1) acc += __shfl_down_sync(0xffffffffu, acc, o);
                if (lane == 0) {
                    if (n < MEL) out[(b * TDEC + t) * MEL + n] = acc + melb[n];
                    else out[B * TDEC * MEL + b * TDEC + t] = acc + stopb[0];
                }
            }
            __syncthreads();
        }
        gbar(++ph);
    }
}

// ---------------- host launch ----------------
extern "C" void kernel_launch(void* const* d_in, const int* in_sizes, int n_in,
                              void* d_out, int out_size) {
    const float* enc    = (const float*)d_in[0];
    const float* mel_in = (const float*)d_in[1];
    const float* pw1    = (const float*)d_in[2];
    const float* pb1    = (const float*)d_in[3];
    const float* pw2    = (const float*)d_in[4];
    const float* pb2    = (const float*)d_in[5];
    const float* awih   = (const float*)d_in[6];
    const float* awhh   = (const float*)d_in[7];
    const float* abih   = (const float*)d_in[8];
    const float* abhh   = (const float*)d_in[9];
    const float* dwih   = (const float*)d_in[10];
    const float* dwhh   = (const float*)d_in[11];
    const float* dbih   = (const float*)d_in[12];
    const float* dbhh   = (const float*)d_in[13];
    const float* qw     = (const float*)d_in[14];
    const float* qb     = (const float*)d_in[15];
    const float* memw   = (const float*)d_in[16];
    const float* memb   = (const float*)d_in[17];
    const float* convw  = (const float*)d_in[18];
    const float* convb  = (const float*)d_in[19];
    const float* lpw    = (const float*)d_in[20];
    const float* lpb    = (const float*)d_in[21];
    const float* vw     = (const float*)d_in[22];
    const float* vb     = (const float*)d_in[23];
    const float* melw   = (const float*)d_in[24];
    const float* melb   = (const float*)d_in[25];
    const float* stopw  = (const float*)d_in[26];
    const float* stopb  = (const float*)d_in[27];
    float* out = (float*)d_out;

    int dev = 0;
    cudaGetDevice(&dev);
    int nsm = 0;
    cudaDeviceGetAttribute(&nsm, cudaDevAttrMultiProcessorCount, dev);
    int occ = 0;
    cudaOccupancyMaxActiveBlocksPerMultiprocessor(&occ, persist_kernel, 256, 0);
    if (occ < 1) occ = 1;
    if (occ > 2) occ = 2;
    int nblk = nsm * occ;

    init_state_kernel<<<64, 256>>>();
    pack_weights_kernel<<<(G * KDEC + 255) / 256, 256>>>(awih, awhh, abih, abhh,
                                                         dwih, dwhh, dbih, dbhh);
    mproj_kernel<<<dim3(8, (B * TENC) / 64), 256>>>(enc, memw, memb);
    persist_kernel<<<nblk, 256>>>(enc, mel_in, pw1, pb1, pw2, pb2, qw, qb,
                                  convw, convb, lpw, lpb, vw, vb,
                                  melw, melb, stopw, stopb, out);
}

// round 13
// speedup vs baseline: 1.2520x; 1.0457x over previous
#include <cuda_runtime.h>
#include <math.h>

#define B 64
#define TENC 300
#define TDEC 500
#define D 512
#define MEL 80
#define PRE 256
#define CLOC 32
#define KW 31
#define G 2048
#define KATT 1280
#define KDEC 1536
#define NSPLIT 8
#define QSPLIT 4
#define CHUNK 75
#define NCHUNK 4

// ---------------- persistent device state ----------------
__device__ float g_xatt[B * KATT];          // [pm(256) | ctx(512) | h_att(512)]
__device__ float g_xdec[B * KDEC];          // [h_att(512) | ctx(512) | h_dec(512)]
__device__ float g_catt[B * D];
__device__ float g_cdec[B * D];
__device__ float g_a[B * TENC];
__device__ float g_acum[B * TENC];
__device__ float g_e[B * TENC];
__device__ float g_parts[NSPLIT * B * G];
__device__ float g_qpart[QSPLIT * B * D];
__device__ float g_mproj[B * TENC * D];
__device__ float g_attW[G * KATT];
__device__ float g_decW[G * KDEC];
__device__ float g_attB[G];
__device__ float g_decB[G];
__device__ unsigned g_count;
__device__ volatile unsigned g_sense;

__device__ __forceinline__ float sigm(float x) { return 1.f / (1.f + expf(-x)); }
// fast tanh used ONLY in the attention-energy stage
__device__ __forceinline__ float ftanh(float x) {
    float e = __expf(-2.f * fabsf(x));
    float r = (1.f - e) / (1.f + e);
    return x < 0.f ? -r : r;
}

// ---------------- grid barrier (proven) ----------------
__device__ __forceinline__ void gbar(unsigned ph) {
    __syncthreads();
    if (threadIdx.x == 0) {
        __threadfence();
        if (atomicAdd(&g_count, 1u) == gridDim.x - 1) {
            g_count = 0u;
            __threadfence();
            g_sense = ph;
        } else {
            while (g_sense < ph) { __nanosleep(32); }
            __threadfence();
        }
    }
    __syncthreads();
}

// ---------------- init / pack ----------------
__global__ void init_state_kernel() {
    int i = blockIdx.x * blockDim.x + threadIdx.x;
    int n = gridDim.x * blockDim.x;
    for (int j = i; j < B * KATT; j += n) g_xatt[j] = 0.f;
    for (int j = i; j < B * KDEC; j += n) g_xdec[j] = 0.f;
    for (int j = i; j < B * D; j += n) { g_catt[j] = 0.f; g_cdec[j] = 0.f; }
    for (int j = i; j < B * TENC; j += n) { g_a[j] = 0.f; g_acum[j] = 0.f; }
    if (i == 0) { g_count = 0u; g_sense = 0u; }
}

__global__ void pack_weights_kernel(const float* __restrict__ awih, const float* __restrict__ awhh,
                                    const float* __restrict__ abih, const float* __restrict__ abhh,
                                    const float* __restrict__ dwih, const float* __restrict__ dwhh,
                                    const float* __restrict__ dbih, const float* __restrict__ dbhh) {
    int idx = blockIdx.x * blockDim.x + threadIdx.x;
    if (idx < G * KATT) {
        int j = idx / KATT, k = idx % KATT;
        g_attW[idx] = (k < 768) ? awih[j * 768 + k] : awhh[j * 512 + (k - 768)];
    }
    if (idx < G * KDEC) {
        int j = idx / KDEC, k = idx % KDEC;
        g_decW[idx] = (k < 1024) ? dwih[j * 1024 + k] : dwhh[j * 512 + (k - 1024)];
    }
    if (idx < G) {
        g_attB[idx] = abih[idx] + abhh[idx];
        g_decB[idx] = dbih[idx] + dbhh[idx];
    }
}

// ---------------- 64x64 tile SGEMM piece (256 threads, global-load prefetch) ----------------
#define XSTRIDE 68
__device__ __forceinline__ void gemm_tile64(
    const float* __restrict__ X, int ldx,
    const float* __restrict__ W, int ldw,
    float* __restrict__ C, int ldc,
    int n0, int k0, int kChunk,
    const float* __restrict__ bias, float* sm) {
    float* Xs = sm;                       // [16][68]
    float* Ws = sm + 16 * XSTRIDE;        // [16][68]
    const int tid = threadIdx.x;
    const int tx = tid & 15, ty = tid >> 4;
    const int lr = tid >> 2, lc = (tid & 3) * 4;
    float acc[4][4];
#pragma unroll
    for (int i = 0; i < 4; i++)
#pragma unroll
        for (int j = 0; j < 4; j++) acc[i][j] = 0.f;

    const float* Xp = X + (long)lr * ldx + k0 + lc;
    const float* Wp = W + (long)(n0 + lr) * ldw + k0 + lc;

    float4 xa = *(const float4*)Xp;
    float4 wa = *(const float4*)Wp;

    for (int kk = 0; kk < kChunk; kk += 16) {
        __syncthreads();
        Xs[(lc + 0) * XSTRIDE + lr] = xa.x; Xs[(lc + 1) * XSTRIDE + lr] = xa.y;
        Xs[(lc + 2) * XSTRIDE + lr] = xa.z; Xs[(lc + 3) * XSTRIDE + lr] = xa.w;
        Ws[(lc + 0) * XSTRIDE + lr] = wa.x; Ws[(lc + 1) * XSTRIDE + lr] = wa.y;
        Ws[(lc + 2) * XSTRIDE + lr] = wa.z; Ws[(lc + 3) * XSTRIDE + lr] = wa.w;
        __syncthreads();
        if (kk + 16 < kChunk) {            // prefetch next tile; latency hidden by FMAs
            xa = *(const float4*)(Xp + kk + 16);
            wa = *(const float4*)(Wp + kk + 16);
        }
#pragma unroll
        for (int k = 0; k < 16; k++) {
            float xr[4], wr[4];
#pragma unroll
            for (int i = 0; i < 4; i++) xr[i] = Xs[k * XSTRIDE + ty * 4 + i];
#pragma unroll
            for (int j = 0; j < 4; j++) wr[j] = Ws[k * XSTRIDE + tx * 4 + j];
#pragma unroll
            for (int i = 0; i < 4; i++)
#pragma unroll
                for (int j = 0; j < 4; j++) acc[i][j] = fmaf(xr[i], wr[j], acc[i][j]);
        }
    }
    float bv[4] = {0.f, 0.f, 0.f, 0.f};
    if (bias) {
#pragma unroll
        for (int j = 0; j < 4; j++) bv[j] = bias[n0 + tx * 4 + j];
    }
#pragma unroll
    for (int i = 0; i < 4; i++) {
        float4 o;
        o.x = acc[i][0] + bv[0]; o.y = acc[i][1] + bv[1];
        o.z = acc[i][2] + bv[2]; o.w = acc[i][3] + bv[3];
        *(float4*)&C[(long)(ty * 4 + i) * ldc + n0 + tx * 4] = o;
    }
}

// ---------------- mproj = enc @ mem_w^T + mem_b (once per replay) ----------------
__global__ __launch_bounds__(256) void mproj_kernel(const float* __restrict__ enc,
                                                    const float* __restrict__ memw,
                                                    const float* __restrict__ memb) {
    __shared__ float sm[2 * 16 * XSTRIDE];
    int m0 = blockIdx.y * 64;
    gemm_tile64(enc + (long)m0 * D, D, memw, D, g_mproj + (long)m0 * D, D,
                blockIdx.x * 64, 0, D, memb, sm);
}

// ---------------- the persistent decoder ----------------
__global__ __launch_bounds__(256, 2) void persist_kernel(
    const float* __restrict__ enc, const float* __restrict__ mel_in,
    const float* __restrict__ pw1, const float* __restrict__ pb1,
    const float* __restrict__ pw2, const float* __restrict__ pb2,
    const float* __restrict__ qw, const float* __restrict__ qb,
    const float* __restrict__ convw, const float* __restrict__ convb,
    const float* __restrict__ lpw, const float* __restrict__ lpb,
    const float* __restrict__ vw, const float* __restrict__ vb,
    const float* __restrict__ melw, const float* __restrict__ melb,
    const float* __restrict__ stopw, const float* __restrict__ stopb,
    float* __restrict__ out) {
    __shared__ float sm[3072];   // 12.3 KB
    const int tid = threadIdx.x;
    unsigned ph = 0;

    for (int t = 0; t <= TDEC; t++) {
        // ---- Stage AH: prenet(t) on units 0..63 ; dec-LSTM+mel(t-1) on units 64..127 ----
        for (int u = blockIdx.x; u < 128; u += gridDim.x) {
            if (u < 64) {
                if (t < TDEC) {
                    const int b = u;
                    float* melS = sm;
                    float* h1 = sm + 128;
                    if (tid < MEL) melS[tid] = mel_in[(b * TDEC + t) * MEL + tid];
                    __syncthreads();
                    float acc = pb1[tid];
                    const float* wr = pw1 + tid * MEL;
#pragma unroll 8
                    for (int k = 0; k < MEL; k++) acc = fmaf(melS[k], wr[k], acc);
                    h1[tid] = fmaxf(acc, 0.f);
                    __syncthreads();
                    float acc2 = pb2[tid];
                    const float* w2r = pw2 + tid * PRE;
#pragma unroll 8
                    for (int k = 0; k < PRE; k++) acc2 = fmaf(h1[k], w2r[k], acc2);
                    g_xatt[b * KATT + tid] = fmaxf(acc2, 0.f);
                    __syncthreads();
                }
            } else {
                if (t > 0) {
                    const int b = u - 64;
                    const int tp = t - 1;
                    float* hS = sm;  // 512
                    for (int uu = tid; uu < D; uu += 256) {
                        float gi = 0.f, gf = 0.f, gg = 0.f, go = 0.f;
#pragma unroll
                        for (int s = 0; s < NSPLIT; s++) {
                            const float* ps = g_parts + (long)s * (B * G) + b * G;
                            gi += ps[uu]; gf += ps[uu + 512]; gg += ps[uu + 1024]; go += ps[uu + 1536];
                        }
                        gi += g_decB[uu]; gf += g_decB[uu + 512];
                        gg += g_decB[uu + 1024]; go += g_decB[uu + 1536];
                        float c = g_cdec[b * D + uu];
                        c = sigm(gf) * c + sigm(gi) * tanhf(gg);
                        float h = sigm(go) * tanhf(c);
                        g_cdec[b * D + uu] = c;
                        g_xdec[b * KDEC + 1024 + uu] = h;
                        hS[uu] = h;
                    }
                    __syncthreads();
                    const int warp = tid >> 5, lane = tid & 31;
                    for (int n = warp; n < MEL + 1; n += 8) {
                        const float* w = (n < MEL) ? (melw + n * D) : stopw;
                        float acc = 0.f;
#pragma unroll
                        for (int k = lane * 4; k < D; k += 128) {
                            float4 wv = *(const float4*)(w + k);
                            acc = fmaf(hS[k + 0], wv.x, acc);
                            acc = fmaf(hS[k + 1], wv.y, acc);
                            acc = fmaf(hS[k + 2], wv.z, acc);
                            acc = fmaf(hS[k + 3], wv.w, acc);
                        }
#pragma unroll
                        for (int o = 16; o; o >>= 1) acc += __shfl_down_sync(0xffffffffu, acc, o);
                        if (lane == 0) {
                            if (n < MEL) out[(b * TDEC + tp) * MEL + n] = acc + melb[n];
                            else out[B * TDEC * MEL + b * TDEC + tp] = acc + stopb[0];
                        }
                    }
                    __syncthreads();
                }
            }
        }
        if (t == TDEC) break;           // last dec-LSTM done; finished
        gbar(++ph);

        // ---- Stage B: att gate GEMM  [64,1280]x[2048,1280]^T, K-split 8 ----
        for (int u = blockIdx.x; u < 32 * NSPLIT; u += gridDim.x) {
            int nt = u & 31, ks = u >> 5;
            gemm_tile64(g_xatt, KATT, g_attW, KATT,
                        g_parts + (long)ks * (B * G), G,
                        nt * 64, ks * (KATT / NSPLIT), KATT / NSPLIT, nullptr, sm);
        }
        gbar(++ph);

        // ---- Stage C: att LSTM update (128 blocks: b x half) ----
        for (int u = blockIdx.x; u < 128; u += gridDim.x) {
            const int b = u >> 1;
            const int uu = (u & 1) * 256 + tid;
            float gi = 0.f, gf = 0.f, gg = 0.f, go = 0.f;
#pragma unroll
            for (int s = 0; s < NSPLIT; s++) {
                const float* ps = g_parts + (long)s * (B * G) + b * G;
                gi += ps[uu]; gf += ps[uu + 512]; gg += ps[uu + 1024]; go += ps[uu + 1536];
            }
            gi += g_attB[uu]; gf += g_attB[uu + 512];
            gg += g_attB[uu + 1024]; go += g_attB[uu + 1536];
            float c = g_catt[b * D + uu];
            c = sigm(gf) * c + sigm(gi) * tanhf(gg);
            float h = sigm(go) * tanhf(c);
            g_catt[b * D + uu] = c;
            g_xatt[b * KATT + 768 + uu] = h;
            g_xdec[b * KDEC + uu] = h;
        }
        gbar(++ph);

        // ---- Stage D: q = h_att @ q_w^T, K-split 4 ----
        for (int u = blockIdx.x; u < 8 * QSPLIT; u += gridDim.x) {
            int nt = u & 7, ks = u >> 3;
            gemm_tile64(g_xdec, KDEC, qw, D,
                        g_qpart + (long)ks * (B * D), D,
                        nt * 64, ks * (D / QSPLIT), D / QSPLIT, nullptr, sm);
        }
        gbar(++ph);

        // ---- Stage E: conv (fused, in-smem) + energy = v . tanh(q + mproj + loc_proj) ----
        for (int u = blockIdx.x; u < B * NCHUNK; u += gridDim.x) {
            const int b = u / NCHUNK;
            const int t0 = (u % NCHUNK) * CHUNK;
            float* aS = sm;                       // 300
            float* acS = sm + 304;                // 300
            float* convS = sm + 608;              // [32][75] = 2400
            float* red = sm + 3008;               // [8][5]
            for (int i = tid; i < TENC; i += 256) {
                aS[i] = g_a[b * TENC + i];
                acS[i] = g_acum[b * TENC + i];
            }
            __syncthreads();
            for (int i = tid; i < CLOC * CHUNK; i += 256) {
                int c = i / CHUNK, tl = i % CHUNK;
                int tt = t0 + tl;
                const float* w0 = convw + c * 62;
                const float* w1 = w0 + KW;
                float s = convb[c];
                int klo = max(0, 15 - tt);
                int khi = min(KW, TENC + 15 - tt);
                for (int k = klo; k < khi; k++) {
                    int tj = tt - 15 + k;
                    s = fmaf(aS[tj], w0[k], s);
                    s = fmaf(acS[tj], w1[k], s);
                }
                convS[c * CHUNK + tl] = s;
            }
            const int d0 = tid, d1 = tid + 256;
            float P0[CLOC], P1[CLOC];
#pragma unroll
            for (int c = 0; c < CLOC; c++) {
                P0[c] = lpw[d0 * CLOC + c];
                P1[c] = lpw[d1 * CLOC + c];
            }
            float base0 = qb[d0] + lpb[d0];
            float base1 = qb[d1] + lpb[d1];
#pragma unroll
            for (int s = 0; s < QSPLIT; s++) {
                base0 += g_qpart[(long)s * (B * D) + b * D + d0];
                base1 += g_qpart[(long)s * (B * D) + b * D + d1];
            }
            const float v0 = vw[d0], v1 = vw[d1];
            __syncthreads();
            for (int tb = 0; tb < CHUNK; tb += 5) {
                float s0[5], s1[5];
#pragma unroll
                for (int j = 0; j < 5; j++) {
                    int tt = t0 + tb + j;
                    s0[j] = base0 + g_mproj[(long)(b * TENC + tt) * D + d0];
                    s1[j] = base1 + g_mproj[(long)(b * TENC + tt) * D + d1];
                }
#pragma unroll
                for (int c = 0; c < CLOC; c++) {
#pragma unroll
                    for (int j = 0; j < 5; j++) {
                        float cv = convS[c * CHUNK + tb + j];
                        s0[j] = fmaf(P0[c], cv, s0[j]);
                        s1[j] = fmaf(P1[c], cv, s1[j]);
                    }
                }
#pragma unroll
                for (int j = 0; j < 5; j++) {
                    float r = v0 * ftanh(s0[j]) + v1 * ftanh(s1[j]);
#pragma unroll
                    for (int o = 16; o; o >>= 1) r += __shfl_down_sync(0xffffffffu, r, o);
                    if ((tid & 31) == 0) red[(tid >> 5) * 5 + j] = r;
                }
                __syncthreads();
                if (tid < 5) {
                    float r = 0.f;
#pragma unroll
                    for (int w = 0; w < 8; w++) r += red[w * 5 + tid];
                    g_e[b * TENC + t0 + tb + tid] = r + vb[0];
                }
                __syncthreads();
            }
        }
        gbar(++ph);

        // ---- Stage F (fused): local softmax + ctx slice (256 blocks: b x 128-d) ----
        for (int u = blockIdx.x; u < 256; u += gridDim.x) {
            const int b = u >> 2;
            const int dq = u & 3;
            float* aS = sm;            // 300
            float* part = sm + 304;    // [2][128]
            float* red = sm + 564;     // 8
            float* bval = sm + 574;
            float x0 = g_e[b * TENC + tid];
            float x1 = (tid + 256 < TENC) ? g_e[b * TENC + tid + 256] : -1e30f;
            float m = fmaxf(x0, x1);
#pragma unroll
            for (int o = 16; o; o >>= 1) m = fmaxf(m, __shfl_xor_sync(0xffffffffu, m, o));
            if ((tid & 31) == 0) red[tid >> 5] = m;
            __syncthreads();
            if (tid == 0) {
                float mm = red[0];
#pragma unroll
                for (int w = 1; w < 8; w++) mm = fmaxf(mm, red[w]);
                bval[0] = mm;
            }
            __syncthreads();
            const float M = bval[0];
            float e0 = expf(x0 - M);
            float e1 = (tid + 256 < TENC) ? expf(x1 - M) : 0.f;
            float s = e0 + e1;
#pragma unroll
            for (int o = 16; o; o >>= 1) s += __shfl_xor_sync(0xffffffffu, s, o);
            if ((tid & 31) == 0) red[tid >> 5] = s;
            __syncthreads();
            if (tid == 0) {
                float ss = 0.f;
#pragma unroll
                for (int w = 0; w < 8; w++) ss += red[w];
                bval[0] = 1.f / ss;
            }
            __syncthreads();
            const float inv = bval[0];
            float a0 = e0 * inv;
            aS[tid] = a0;
            if (tid + 256 < TENC) aS[tid + 256] = e1 * inv;
            if (dq == 0) {              // single writer commits a / a_cum
                g_a[b * TENC + tid] = a0;
                g_acum[b * TENC + tid] += a0;
                if (tid + 256 < TENC) {
                    float a1 = e1 * inv;
                    g_a[b * TENC + tid + 256] = a1;
                    g_acum[b * TENC + tid + 256] += a1;
                }
            }
            __syncthreads();
            const int dl = tid & 127;
            const int th = tid >> 7;                 // t-half 0/1
            const float* ep = enc + (long)b * TENC * D + dq * 128 + dl;
            float acc = 0.f;
#pragma unroll 10
            for (int tt = th * 150; tt < th * 150 + 150; tt++)
                acc = fmaf(aS[tt], ep[(long)tt * D], acc);
            part[th * 128 + dl] = acc;
            __syncthreads();
            if (tid < 128) {
                float c = part[tid] + part[128 + tid];
                g_xatt[b * KATT + 256 + dq * 128 + tid] = c;
                g_xdec[b * KDEC + 512 + dq * 128 + tid] = c;
            }
            __syncthreads();
        }
        gbar(++ph);

        // ---- Stage G: dec gate GEMM  [64,1536]x[2048,1536]^T, K-split 8 ----
        for (int u = blockIdx.x; u < 32 * NSPLIT; u += gridDim.x) {
            int nt = u & 31, ks = u >> 5;
            gemm_tile64(g_xdec, KDEC, g_decW, KDEC,
                        g_parts + (long)ks * (B * G), G,
                        nt * 64, ks * (KDEC / NSPLIT), KDEC / NSPLIT, nullptr, sm);
        }
        gbar(++ph);
        // loop around: next AH window runs dec-LSTM(t) + prenet(t+1)
    }
}

// ---------------- host launch ----------------
extern "C" void kernel_launch(void* const* d_in, const int* in_sizes, int n_in,
                              void* d_out, int out_size) {
    const float* enc    = (const float*)d_in[0];
    const float* mel_in = (const float*)d_in[1];
    const float* pw1    = (const float*)d_in[2];
    const float* pb1    = (const float*)d_in[3];
    const float* pw2    = (const float*)d_in[4];
    const float* pb2    = (const float*)d_in[5];
    const float* awih   = (const float*)d_in[6];
    const float* awhh   = (const float*)d_in[7];
    const float* abih   = (const float*)d_in[8];
    const float* abhh   = (const float*)d_in[9];
    const float* dwih   = (const float*)d_in[10];
    const float* dwhh   = (const float*)d_in[11];
    const float* dbih   = (const float*)d_in[12];
    const float* dbhh   = (const float*)d_in[13];
    const float* qw     = (const float*)d_in[14];
    const float* qb     = (const float*)d_in[15];
    const float* memw   = (const float*)d_in[16];
    const float* memb   = (const float*)d_in[17];
    const float* convw  = (const float*)d_in[18];
    const float* convb  = (const float*)d_in[19];
    const float* lpw    = (const float*)d_in[20];
    const float* lpb    = (const float*)d_in[21];
    const float* vw     = (const float*)d_in[22];
    const float* vb     = (const float*)d_in[23];
    const float* melw   = (const float*)d_in[24];
    const float* melb   = (const float*)d_in[25];
    const float* stopw  = (const float*)d_in[26];
    const float* stopb  = (const float*)d_in[27];
    float* out = (float*)d_out;

    int dev = 0;
    cudaGetDevice(&dev);
    int nsm = 0;
    cudaDeviceGetAttribute(&nsm, cudaDevAttrMultiProcessorCount, dev);
    int occ = 0;
    cudaOccupancyMaxActiveBlocksPerMultiprocessor(&occ, persist_kernel, 256, 0);
    if (occ < 1) occ = 1;
    if (occ > 2) occ = 2;
    int nblk = nsm * occ;

    init_state_kernel<<<64, 256>>>();
    pack_weights_kernel<<<(G * KDEC + 255) / 256, 256>>>(awih, awhh, abih, abhh,
                                                         dwih, dwhh, dbih, dbhh);
    mproj_kernel<<<dim3(8, (B * TENC) / 64), 256>>>(enc, memw, memb);
    persist_kernel<<<nblk, 256>>>(enc, mel_in, pw1, pb1, pw2, pb2, qw, qb,
                                  convw, convb, lpw, lpb, vw, vb,
                                  melw, melb, stopw, stopb, out);
}